// round 9
// baseline (speedup 1.0000x reference)
#include <cuda_runtime.h>
#include <cuda_fp16.h>
#include <cstdint>

// MeanPooling == batched GEMM + row scale. Warp-specialized fp16 mma.sync:
//   warps 0-3: cp.async fp32 ring (3 slots) + fp32->fp16 smem convert
//   warps 4-7: ldmatrix + MMA (each warp: 32 M-rows x 64 N-cols)
// Handshake via named barriers (FULL/EMPTY per fp16 buffer).
//   d_in[0] doc_state      [B=32, L=2048, D=256] fp32   (B operand)
//   d_in[1] entity_mapping [B=32, E=256,  L=2048] fp32  (A operand)
//   d_in[2] entity_lens    [B=32, E=256] fp32
// Output [B, E, D] fp32 = (emap @ doc) / lens

#define BATCH 32
#define E_DIM 256
#define L_DIM 2048
#define D_DIM 256

#define TILE_M 128
#define TILE_N 64
#define CHUNK 32
#define NCHUNK (L_DIM / CHUNK)      // 64

// fp32 staging ring: linear tiles, 3 slots
#define A32_BYTES (TILE_M * CHUNK * 4)     // 16384
#define B32_BYTES (CHUNK * TILE_N * 4)     // 8192
#define SLOT_BYTES (A32_BYTES + B32_BYTES) // 24576
#define RING_BYTES (3 * SLOT_BYTES)        // 73728

// fp16 compute tiles (padded strides, conflict-free ldmatrix)
#define A_STRIDE_B 80                      // bytes per A row (32 halfs + pad)
#define B_STRIDE_B 144                     // bytes per B row (64 halfs + pad)
#define A16_BYTES (TILE_M * A_STRIDE_B)    // 10240
#define B16_BYTES (CHUNK * B_STRIDE_B)     // 4608
#define F16_STAGE (A16_BYTES + B16_BYTES)  // 14848
#define OFF_F16 RING_BYTES
#define SMEM_TOTAL (RING_BYTES + 2 * F16_STAGE)   // 103424

// named barrier ids
#define BAR_FULL0  1
#define BAR_FULL1  2
#define BAR_EMPTY0 3
#define BAR_EMPTY1 4
#define BAR_PROD   5

#define BAR_SYNC(id, cnt) \
    asm volatile("bar.sync %0, %1;" :: "r"(id), "r"(cnt) : "memory")
#define BAR_ARRIVE(id, cnt) \
    asm volatile("bar.arrive %0, %1;" :: "r"(id), "r"(cnt) : "memory")

static __device__ __forceinline__ uint32_t smem_u32(const void* p) {
    uint32_t a;
    asm("{ .reg .u64 t; cvta.to.shared.u64 t, %1; cvt.u32.u64 %0, t; }"
        : "=r"(a) : "l"(p));
    return a;
}

#define CP_ASYNC16(smem_addr, gptr) \
    asm volatile("cp.async.cg.shared.global [%0], [%1], 16;" \
                 :: "r"(smem_addr), "l"(gptr) : "memory")
#define CP_COMMIT() asm volatile("cp.async.commit_group;" ::: "memory")
#define CP_WAIT2()  asm volatile("cp.async.wait_group 2;" ::: "memory")

#define LDSM_X4(r0, r1, r2, r3, addr) \
    asm volatile("ldmatrix.sync.aligned.m8n8.x4.shared.b16 {%0,%1,%2,%3}, [%4];" \
                 : "=r"(r0), "=r"(r1), "=r"(r2), "=r"(r3) : "r"(addr))

#define LDSM_X4_T(r0, r1, r2, r3, addr) \
    asm volatile("ldmatrix.sync.aligned.m8n8.x4.trans.shared.b16 {%0,%1,%2,%3}, [%4];" \
                 : "=r"(r0), "=r"(r1), "=r"(r2), "=r"(r3) : "r"(addr))

#define MMA16816(d, a0, a1, a2, a3, b0, b1) \
    asm volatile("mma.sync.aligned.m16n8k16.row.col.f32.f16.f16.f32 " \
                 "{%0,%1,%2,%3}, {%4,%5,%6,%7}, {%8,%9}, {%0,%1,%2,%3};" \
                 : "+f"((d)[0]), "+f"((d)[1]), "+f"((d)[2]), "+f"((d)[3]) \
                 : "r"(a0), "r"(a1), "r"(a2), "r"(a3), "r"(b0), "r"(b1))

static __device__ __forceinline__ uint32_t cvt2(float x, float y)
{
    __half hx = __float2half_rn(x);
    __half hy = __float2half_rn(y);
    return (uint32_t)__half_as_ushort(hx) | ((uint32_t)__half_as_ushort(hy) << 16);
}

__global__ void __launch_bounds__(256, 2)
mean_pool_hmma(const float* __restrict__ doc,
               const float* __restrict__ emap,
               const float* __restrict__ lens,
               float* __restrict__ out)
{
    extern __shared__ char smem[];
    const uint32_t sbase = smem_u32(smem);

    const int tid = threadIdx.x;
    const int wid = tid >> 5;
    const int lid = tid & 31;

    const int b     = blockIdx.z;
    const int tileM = blockIdx.y * TILE_M;
    const int tileN = blockIdx.x * TILE_N;

    const float* A  = emap + (size_t)b * E_DIM * L_DIM + (size_t)tileM * L_DIM;
    const float* Bm = doc  + (size_t)b * L_DIM * D_DIM + tileN;
    float*       C  = out  + (size_t)b * E_DIM * D_DIM;

    if (wid < 4) {
        // ===================== PRODUCER (threads 0..127) =====================
        const int ptid = tid;   // 0..127

        // cp.async addressing: A 1024 16B-units (8/thread), B 512 (4/thread)
        #define P_ISSUE(k0, slot) do {                                          \
            const uint32_t sA = sbase + (uint32_t)((slot) * SLOT_BYTES);        \
            const uint32_t sB = sA + A32_BYTES;                                 \
            _Pragma("unroll")                                                   \
            for (int i = 0; i < 8; i++) {                                       \
                const int u = ptid + 128 * i;                                   \
                CP_ASYNC16(sA + u * 16,                                         \
                           &A[(size_t)(u >> 3) * L_DIM + (k0) + (u & 7) * 4]);  \
            }                                                                   \
            _Pragma("unroll")                                                   \
            for (int i = 0; i < 4; i++) {                                       \
                const int u = ptid + 128 * i;                                   \
                CP_ASYNC16(sB + u * 16,                                         \
                           &Bm[(size_t)((k0) + (u >> 4)) * D_DIM + (u & 15) * 4]); \
            }                                                                   \
        } while (0)

        #define P_CONVERT(slot, buf) do {                                       \
            char* srcA = smem + (slot) * SLOT_BYTES;                            \
            char* srcB = srcA + A32_BYTES;                                      \
            char* dstA = smem + OFF_F16 + (buf) * F16_STAGE;                    \
            char* dstB = dstA + A16_BYTES;                                      \
            _Pragma("unroll")                                                   \
            for (int i = 0; i < 16; i++) {                                      \
                const int p = ptid + 128 * i;                                   \
                float2 v = *reinterpret_cast<const float2*>(srcA + p * 8);      \
                *reinterpret_cast<uint32_t*>(dstA + (p >> 4) * A_STRIDE_B       \
                                             + (p & 15) * 4) = cvt2(v.x, v.y);  \
            }                                                                   \
            _Pragma("unroll")                                                   \
            for (int i = 0; i < 8; i++) {                                       \
                const int p = ptid + 128 * i;                                   \
                float2 v = *reinterpret_cast<const float2*>(srcB + p * 8);      \
                *reinterpret_cast<uint32_t*>(dstB + (p >> 5) * B_STRIDE_B       \
                                             + (p & 31) * 4) = cvt2(v.x, v.y);  \
            }                                                                   \
        } while (0)

        // prologue: chunks 0 and 1 in flight
        P_ISSUE(0, 0);
        CP_COMMIT();
        P_ISSUE(CHUNK, 1);
        CP_COMMIT();

        int slot = 0;
        for (int c = 0; c < NCHUNK; c++) {
            const int s = c & 1;

            // wait for fp16 buffer s to be free; this rendezvous also orders
            // all producers past convert(c-1), making ring-slot reuse safe.
            if (c >= 2) BAR_SYNC(s ? BAR_EMPTY1 : BAR_EMPTY0, 256);
            else        BAR_SYNC(BAR_PROD, 128);

            // issue chunk c+2 (empty commit keeps group accounting uniform)
            if (c + 2 < NCHUNK) {
                const int slot2 = (slot + 2 >= 3) ? slot - 1 : slot + 2;
                P_ISSUE((c + 2) * CHUNK, slot2);
            }
            CP_COMMIT();

            // chunk c resident after <=2 outstanding groups; the producer
            // barrier makes OTHER threads' copies visible before we read.
            CP_WAIT2();
            BAR_SYNC(BAR_PROD, 128);

            P_CONVERT(slot, s);
            BAR_ARRIVE(s ? BAR_FULL1 : BAR_FULL0, 256);

            slot = (slot + 1 == 3) ? 0 : slot + 1;
        }
    } else {
        // ===================== CONSUMER (threads 128..255) ===================
        const int cwid = wid - 4;           // 0..3, owns M rows cwid*32..+31

        float acc[2][8][4] = {};            // [m16][n8-tile][frag]

        const uint32_t a_lrow = (uint32_t)(cwid * 32 + (lid & 15));
        const uint32_t a_lcol = (uint32_t)((lid >> 4) * 16);       // bytes
        const uint32_t b_lrow = (uint32_t)(lid & 15);
        const uint32_t b_lcol = (uint32_t)((lid >> 4) * 16);       // bytes

        for (int c = 0; c < NCHUNK; c++) {
            const int s = c & 1;
            BAR_SYNC(s ? BAR_FULL1 : BAR_FULL0, 256);

            const uint32_t f16 = sbase + OFF_F16 + (uint32_t)(s * F16_STAGE);
            const uint32_t aT  = f16;
            const uint32_t bT  = f16 + A16_BYTES;

            #pragma unroll
            for (int ko = 0; ko < 2; ko++) {
                const uint32_t akb = a_lcol + (uint32_t)(ko * 32);
                uint32_t a[2][4];
                #pragma unroll
                for (int mi = 0; mi < 2; mi++) {
                    const uint32_t ao = (a_lrow + mi * 16) * A_STRIDE_B + akb;
                    LDSM_X4(a[mi][0], a[mi][1], a[mi][2], a[mi][3], aT + ao);
                }
                #pragma unroll
                for (int nt = 0; nt < 4; nt++) {
                    const uint32_t bo = (b_lrow + (uint32_t)(ko * 16)) * B_STRIDE_B
                                        + b_lcol + (uint32_t)(nt * 32);
                    uint32_t b0, b1, b2, b3;
                    LDSM_X4_T(b0, b1, b2, b3, bT + bo);
                    #pragma unroll
                    for (int mi = 0; mi < 2; mi++) {
                        MMA16816(acc[mi][nt * 2],     a[mi][0], a[mi][1], a[mi][2], a[mi][3], b0, b1);
                        MMA16816(acc[mi][nt * 2 + 1], a[mi][0], a[mi][1], a[mi][2], a[mi][3], b2, b3);
                    }
                }
            }

            BAR_ARRIVE(s ? BAR_EMPTY1 : BAR_EMPTY0, 256);
        }

        // ---- epilogue: scale by 1/len, store ----
        #pragma unroll
        for (int mi = 0; mi < 2; mi++) {
            const int r0 = tileM + cwid * 32 + mi * 16 + (lid >> 2);
            const int r1 = r0 + 8;
            const float inv0 = 1.0f / lens[(size_t)b * E_DIM + r0];
            const float inv1 = 1.0f / lens[(size_t)b * E_DIM + r1];
            #pragma unroll
            for (int j = 0; j < 8; j++) {
                const int col = tileN + j * 8 + (lid & 3) * 2;
                float2 o0 = make_float2(acc[mi][j][0] * inv0, acc[mi][j][1] * inv0);
                float2 o1 = make_float2(acc[mi][j][2] * inv1, acc[mi][j][3] * inv1);
                *reinterpret_cast<float2*>(&C[(size_t)r0 * D_DIM + col]) = o0;
                *reinterpret_cast<float2*>(&C[(size_t)r1 * D_DIM + col]) = o1;
            }
        }
    }
}

extern "C" void kernel_launch(void* const* d_in, const int* in_sizes, int n_in,
                              void* d_out, int out_size)
{
    const float* doc  = (const float*)d_in[0];
    const float* emap = (const float*)d_in[1];
    const float* lens = (const float*)d_in[2];
    float* out = (float*)d_out;

    cudaFuncSetAttribute(mean_pool_hmma,
                         cudaFuncAttributeMaxDynamicSharedMemorySize, SMEM_TOTAL);

    dim3 grid(D_DIM / TILE_N, E_DIM / TILE_M, BATCH);   // (4, 2, 32) = 256 CTAs
    mean_pool_hmma<<<grid, 256, SMEM_TOTAL>>>(doc, emap, lens, out);
}

// round 10
// speedup vs baseline: 1.2854x; 1.2854x over previous
#include <cuda_runtime.h>
#include <cuda_fp16.h>
#include <cstdint>

// MeanPooling == batched GEMM + row scale, all-fp16 mma.sync with a
// cp.async fp32 staging ring (3 slots) feeding a smem convert pass.
// Race-free ordering: wait_group -> __syncthreads -> (compute | convert).
//   d_in[0] doc_state      [B=32, L=2048, D=256] fp32   (B operand)
//   d_in[1] entity_mapping [B=32, E=256,  L=2048] fp32  (A operand)
//   d_in[2] entity_lens    [B=32, E=256] fp32
// Output [B, E, D] fp32 = (emap @ doc) / lens

#define BATCH 32
#define E_DIM 256
#define L_DIM 2048
#define D_DIM 256

#define TILE_M 128
#define TILE_N 64
#define CHUNK 32
#define NCHUNK (L_DIM / CHUNK)      // 64

// fp32 staging ring: linear tiles, 3 slots (chunk k lives in slot k%3)
#define A32_BYTES (TILE_M * CHUNK * 4)     // 16384
#define B32_BYTES (CHUNK * TILE_N * 4)     // 8192
#define SLOT_BYTES (A32_BYTES + B32_BYTES) // 24576
#define RING_BYTES (3 * SLOT_BYTES)        // 73728

// fp16 compute tiles (padded strides, conflict-free ldmatrix)
#define A_STRIDE_B 80                      // bytes per A row (32 halfs + pad)
#define B_STRIDE_B 144                     // bytes per B row (64 halfs + pad)
#define A16_BYTES (TILE_M * A_STRIDE_B)    // 10240
#define B16_BYTES (CHUNK * B_STRIDE_B)     // 4608
#define F16_STAGE (A16_BYTES + B16_BYTES)  // 14848
#define OFF_F16 RING_BYTES
#define SMEM_TOTAL (RING_BYTES + 2 * F16_STAGE)   // 103424

static __device__ __forceinline__ uint32_t smem_u32(const void* p) {
    uint32_t a;
    asm("{ .reg .u64 t; cvta.to.shared.u64 t, %1; cvt.u32.u64 %0, t; }"
        : "=r"(a) : "l"(p));
    return a;
}

#define CP_ASYNC16(smem_addr, gptr) \
    asm volatile("cp.async.cg.shared.global [%0], [%1], 16;" \
                 :: "r"(smem_addr), "l"(gptr) : "memory")
#define CP_COMMIT() asm volatile("cp.async.commit_group;" ::: "memory")
#define CP_WAIT1()  asm volatile("cp.async.wait_group 1;" ::: "memory")

#define LDSM_X4(r0, r1, r2, r3, addr) \
    asm volatile("ldmatrix.sync.aligned.m8n8.x4.shared.b16 {%0,%1,%2,%3}, [%4];" \
                 : "=r"(r0), "=r"(r1), "=r"(r2), "=r"(r3) : "r"(addr))

#define LDSM_X4_T(r0, r1, r2, r3, addr) \
    asm volatile("ldmatrix.sync.aligned.m8n8.x4.trans.shared.b16 {%0,%1,%2,%3}, [%4];" \
                 : "=r"(r0), "=r"(r1), "=r"(r2), "=r"(r3) : "r"(addr))

#define MMA16816(d, a0, a1, a2, a3, b0, b1) \
    asm volatile("mma.sync.aligned.m16n8k16.row.col.f32.f16.f16.f32 " \
                 "{%0,%1,%2,%3}, {%4,%5,%6,%7}, {%8,%9}, {%0,%1,%2,%3};" \
                 : "+f"((d)[0]), "+f"((d)[1]), "+f"((d)[2]), "+f"((d)[3]) \
                 : "r"(a0), "r"(a1), "r"(a2), "r"(a3), "r"(b0), "r"(b1))

static __device__ __forceinline__ uint32_t cvt2(float x, float y)
{
    __half hx = __float2half_rn(x);
    __half hy = __float2half_rn(y);
    return (uint32_t)__half_as_ushort(hx) | ((uint32_t)__half_as_ushort(hy) << 16);
}

__global__ void __launch_bounds__(256, 2)
mean_pool_hmma(const float* __restrict__ doc,
               const float* __restrict__ emap,
               const float* __restrict__ lens,
               float* __restrict__ out)
{
    extern __shared__ char smem[];
    const uint32_t sbase = smem_u32(smem);

    const int tid = threadIdx.x;
    const int wid = tid >> 5;
    const int lid = tid & 31;
    const int wm  = wid & 3;        // 4 warps in M (32 rows each)
    const int wn  = wid >> 2;       // 2 warps in N (32 cols each)

    const int b     = blockIdx.z;
    const int tileM = blockIdx.y * TILE_M;
    const int tileN = blockIdx.x * TILE_N;

    const float* A  = emap + (size_t)b * E_DIM * L_DIM + (size_t)tileM * L_DIM;
    const float* Bm = doc  + (size_t)b * L_DIM * D_DIM + tileN;
    float*       C  = out  + (size_t)b * E_DIM * D_DIM;

    float acc[2][4][4] = {};            // [m16-tile][n8-tile][frag]

    // ldmatrix lane addressing (fp16 buffers)
    const uint32_t a_lrow = (uint32_t)(wm * 32 + (lid & 15));
    const uint32_t a_lcol = (uint32_t)((lid >> 4) * 16);             // bytes
    const uint32_t b_lrow = (uint32_t)(lid & 15);
    const uint32_t b_lcol = (uint32_t)(wn * 64 + (lid >> 4) * 16);   // bytes

    // issue chunk k0 into ring slot `slot`
    #define ISSUE_CHUNK(k0, slot) do {                                         \
        const uint32_t sA = sbase + (uint32_t)((slot) * SLOT_BYTES);           \
        const uint32_t sB = sA + A32_BYTES;                                    \
        _Pragma("unroll")                                                      \
        for (int i = 0; i < 4; i++) {                                          \
            const int u = tid + 256 * i;                                       \
            CP_ASYNC16(sA + u * 16,                                            \
                       &A[(size_t)(u >> 3) * L_DIM + (k0) + (u & 7) * 4]);     \
        }                                                                      \
        _Pragma("unroll")                                                      \
        for (int i = 0; i < 2; i++) {                                          \
            const int u = tid + 256 * i;                                       \
            CP_ASYNC16(sB + u * 16,                                            \
                       &Bm[(size_t)((k0) + (u >> 4)) * D_DIM + (u & 15) * 4]); \
        }                                                                      \
    } while (0)

    // convert ring slot -> fp16 buffer buf (0/1); float4 -> uint2 (STS.64)
    #define CONVERT_CHUNK(slot, buf) do {                                      \
        char* srcA = smem + (slot) * SLOT_BYTES;                               \
        char* srcB = srcA + A32_BYTES;                                         \
        char* dstA = smem + OFF_F16 + (buf) * F16_STAGE;                       \
        char* dstB = dstA + A16_BYTES;                                         \
        _Pragma("unroll")                                                      \
        for (int i = 0; i < 4; i++) {                                          \
            const int f = tid + 256 * i;   /* float4 index, 8 per A row */     \
            float4 v = *reinterpret_cast<const float4*>(srcA + f * 16);        \
            uint2 w = make_uint2(cvt2(v.x, v.y), cvt2(v.z, v.w));              \
            *reinterpret_cast<uint2*>(dstA + (f >> 3) * A_STRIDE_B             \
                                      + (f & 7) * 8) = w;                      \
        }                                                                      \
        _Pragma("unroll")                                                      \
        for (int i = 0; i < 2; i++) {                                          \
            const int f = tid + 256 * i;   /* float4 index, 16 per B row */    \
            float4 v = *reinterpret_cast<const float4*>(srcB + f * 16);        \
            uint2 w = make_uint2(cvt2(v.x, v.y), cvt2(v.z, v.w));              \
            *reinterpret_cast<uint2*>(dstB + (f >> 4) * B_STRIDE_B             \
                                      + (f & 15) * 8) = w;                     \
        }                                                                      \
    } while (0)

    // ---- prologue: chunks 0,1 in flight; convert chunk 0 ----
    ISSUE_CHUNK(0, 0);
    CP_COMMIT();
    ISSUE_CHUNK(CHUNK, 1);
    CP_COMMIT();
    CP_WAIT1();                      // own copies of chunk 0 done
    __syncthreads();                 // everyone's chunk-0 copies visible
    CONVERT_CHUNK(0, 0);

    for (int c = 0; c < NCHUNK; c++) {
        // issue chunk c+2 (slot (c+2)%3); empty commit keeps accounting uniform
        if (c + 2 < NCHUNK) {
            const int slot2 = (c + 2) % 3;
            ISSUE_CHUNK((c + 2) * CHUNK, slot2);
        }
        CP_COMMIT();

        // chunk c+1 resident (own), then barrier -> visible to all threads;
        // barrier also orders convert(c) [prev iter] before compute(c) below.
        CP_WAIT1();
        __syncthreads();

        // ---- compute chunk c from fp16 buffer (c&1) ----
        const uint32_t f16 = sbase + OFF_F16 + (uint32_t)((c & 1) * F16_STAGE);
        const uint32_t aT  = f16;
        const uint32_t bT  = f16 + A16_BYTES;

        #pragma unroll
        for (int ko = 0; ko < 2; ko++) {
            const uint32_t akb = a_lcol + (uint32_t)(ko * 32);
            uint32_t a[2][4];
            #pragma unroll
            for (int mi = 0; mi < 2; mi++) {
                const uint32_t ao = (a_lrow + mi * 16) * A_STRIDE_B + akb;
                LDSM_X4(a[mi][0], a[mi][1], a[mi][2], a[mi][3], aT + ao);
            }
            #pragma unroll
            for (int nt = 0; nt < 2; nt++) {
                const uint32_t bo = (b_lrow + (uint32_t)(ko * 16)) * B_STRIDE_B
                                    + b_lcol + (uint32_t)(nt * 32);
                uint32_t b0, b1, b2, b3;
                LDSM_X4_T(b0, b1, b2, b3, bT + bo);
                #pragma unroll
                for (int mi = 0; mi < 2; mi++) {
                    MMA16816(acc[mi][nt * 2],     a[mi][0], a[mi][1], a[mi][2], a[mi][3], b0, b1);
                    MMA16816(acc[mi][nt * 2 + 1], a[mi][0], a[mi][1], a[mi][2], a[mi][3], b2, b3);
                }
            }
        }

        // ---- convert chunk c+1 into the other fp16 buffer ----
        if (c + 1 < NCHUNK)
            CONVERT_CHUNK((c + 1) % 3, (c + 1) & 1);
    }

    // ---- epilogue: scale by 1/len, store ----
    #pragma unroll
    for (int mi = 0; mi < 2; mi++) {
        const int r0 = tileM + wm * 32 + mi * 16 + (lid >> 2);
        const int r1 = r0 + 8;
        const float inv0 = 1.0f / lens[(size_t)b * E_DIM + r0];
        const float inv1 = 1.0f / lens[(size_t)b * E_DIM + r1];
        #pragma unroll
        for (int j = 0; j < 4; j++) {
            const int col = tileN + wn * 32 + j * 8 + (lid & 3) * 2;
            float2 o0 = make_float2(acc[mi][j][0] * inv0, acc[mi][j][1] * inv0);
            float2 o1 = make_float2(acc[mi][j][2] * inv1, acc[mi][j][3] * inv1);
            *reinterpret_cast<float2*>(&C[(size_t)r0 * D_DIM + col]) = o0;
            *reinterpret_cast<float2*>(&C[(size_t)r1 * D_DIM + col]) = o1;
        }
    }
}

extern "C" void kernel_launch(void* const* d_in, const int* in_sizes, int n_in,
                              void* d_out, int out_size)
{
    const float* doc  = (const float*)d_in[0];
    const float* emap = (const float*)d_in[1];
    const float* lens = (const float*)d_in[2];
    float* out = (float*)d_out;

    cudaFuncSetAttribute(mean_pool_hmma,
                         cudaFuncAttributeMaxDynamicSharedMemorySize, SMEM_TOTAL);

    dim3 grid(D_DIM / TILE_N, E_DIM / TILE_M, BATCH);   // (4, 2, 32) = 256 CTAs
    mean_pool_hmma<<<grid, 256, SMEM_TOTAL>>>(doc, emap, lens, out);
}

// round 11
// speedup vs baseline: 1.4010x; 1.0899x over previous
#include <cuda_runtime.h>
#include <cuda_fp16.h>
#include <cstdint>

// MeanPooling == batched GEMM + row scale, all-fp16 mma.sync.
// A: cp.async fp32 ring (3 slots) -> smem convert to fp16 tiles.
// B: register prefetch (distance 2) -> convert -> fp16 STS (no staging).
//   d_in[0] doc_state      [B=32, L=2048, D=256] fp32   (B operand)
//   d_in[1] entity_mapping [B=32, E=256,  L=2048] fp32  (A operand)
//   d_in[2] entity_lens    [B=32, E=256] fp32
// Output [B, E, D] fp32 = (emap @ doc) / lens

#define BATCH 32
#define E_DIM 256
#define L_DIM 2048
#define D_DIM 256

#define TILE_M 128
#define TILE_N 64
#define CHUNK 32
#define NCHUNK (L_DIM / CHUNK)      // 64

// fp32 staging ring (A only): 3 slots, chunk k in slot k%3
#define A32_BYTES (TILE_M * CHUNK * 4)     // 16384
#define RING_BYTES (3 * A32_BYTES)         // 49152

// fp16 compute tiles (padded strides, conflict-free ldmatrix)
#define A_STRIDE_B 80                      // bytes per A row (32 halfs + pad)
#define B_STRIDE_B 144                     // bytes per B row (64 halfs + pad)
#define A16_BYTES (TILE_M * A_STRIDE_B)    // 10240
#define B16_BYTES (CHUNK * B_STRIDE_B)     // 4608
#define F16_STAGE (A16_BYTES + B16_BYTES)  // 14848
#define OFF_F16 RING_BYTES
#define SMEM_TOTAL (RING_BYTES + 2 * F16_STAGE)   // 78848

static __device__ __forceinline__ uint32_t smem_u32(const void* p) {
    uint32_t a;
    asm("{ .reg .u64 t; cvta.to.shared.u64 t, %1; cvt.u32.u64 %0, t; }"
        : "=r"(a) : "l"(p));
    return a;
}

#define CP_ASYNC16(smem_addr, gptr) \
    asm volatile("cp.async.cg.shared.global [%0], [%1], 16;" \
                 :: "r"(smem_addr), "l"(gptr) : "memory")
#define CP_COMMIT() asm volatile("cp.async.commit_group;" ::: "memory")
#define CP_WAIT1()  asm volatile("cp.async.wait_group 1;" ::: "memory")

#define LDSM_X4(r0, r1, r2, r3, addr) \
    asm volatile("ldmatrix.sync.aligned.m8n8.x4.shared.b16 {%0,%1,%2,%3}, [%4];" \
                 : "=r"(r0), "=r"(r1), "=r"(r2), "=r"(r3) : "r"(addr))

#define LDSM_X4_T(r0, r1, r2, r3, addr) \
    asm volatile("ldmatrix.sync.aligned.m8n8.x4.trans.shared.b16 {%0,%1,%2,%3}, [%4];" \
                 : "=r"(r0), "=r"(r1), "=r"(r2), "=r"(r3) : "r"(addr))

#define MMA16816(d, a0, a1, a2, a3, b0, b1) \
    asm volatile("mma.sync.aligned.m16n8k16.row.col.f32.f16.f16.f32 " \
                 "{%0,%1,%2,%3}, {%4,%5,%6,%7}, {%8,%9}, {%0,%1,%2,%3};" \
                 : "+f"((d)[0]), "+f"((d)[1]), "+f"((d)[2]), "+f"((d)[3]) \
                 : "r"(a0), "r"(a1), "r"(a2), "r"(a3), "r"(b0), "r"(b1))

static __device__ __forceinline__ uint32_t cvt2(float x, float y)
{
    uint32_t r;
    asm("cvt.rn.f16x2.f32 %0, %1, %2;" : "=r"(r) : "f"(y), "f"(x));
    return r;
}

__global__ void __launch_bounds__(256, 2)
mean_pool_hmma(const float* __restrict__ doc,
               const float* __restrict__ emap,
               const float* __restrict__ lens,
               float* __restrict__ out)
{
    extern __shared__ char smem[];
    const uint32_t sbase = smem_u32(smem);

    const int tid = threadIdx.x;
    const int wid = tid >> 5;
    const int lid = tid & 31;
    const int wm  = wid & 3;        // 4 warps in M (32 rows each)
    const int wn  = wid >> 2;       // 2 warps in N (32 cols each)

    const int b     = blockIdx.z;
    const int tileM = blockIdx.y * TILE_M;
    const int tileN = blockIdx.x * TILE_N;

    const float* A  = emap + (size_t)b * E_DIM * L_DIM + (size_t)tileM * L_DIM;
    const float* Bm = doc  + (size_t)b * L_DIM * D_DIM + tileN;
    float*       C  = out  + (size_t)b * E_DIM * D_DIM;

    float acc[2][4][4] = {};            // [m16-tile][n8-tile][frag]

    // B gmem mapping: 512 float4 per chunk, 2/thread: u = tid + 256*i
    const int b_row0 = tid >> 4;            // u = tid
    const int b_row1 = (tid + 256) >> 4;    // u = tid + 256
    const int b_col  = (tid & 15) * 4;

    float4 bcur[2], bnxt[2];

    // ldmatrix lane addressing (fp16 buffers)
    const uint32_t a_lrow = (uint32_t)(wm * 32 + (lid & 15));
    const uint32_t a_lcol = (uint32_t)((lid >> 4) * 16);             // bytes
    const uint32_t b_lrow = (uint32_t)(lid & 15);
    const uint32_t b_lcol = (uint32_t)(wn * 64 + (lid >> 4) * 16);   // bytes

    // issue A chunk k0 into ring slot `slot`
    #define ISSUE_A(k0, slot) do {                                             \
        const uint32_t sA = sbase + (uint32_t)((slot) * A32_BYTES);            \
        _Pragma("unroll")                                                      \
        for (int i = 0; i < 4; i++) {                                          \
            const int u = tid + 256 * i;                                       \
            CP_ASYNC16(sA + u * 16,                                            \
                       &A[(size_t)(u >> 3) * L_DIM + (k0) + (u & 7) * 4]);     \
        }                                                                      \
    } while (0)

    #define LDG_B(k0, dst) do {                                                \
        (dst)[0] = *reinterpret_cast<const float4*>(                           \
            &Bm[(size_t)((k0) + b_row0) * D_DIM + b_col]);                     \
        (dst)[1] = *reinterpret_cast<const float4*>(                           \
            &Bm[(size_t)((k0) + b_row1) * D_DIM + b_col]);                     \
    } while (0)

    // convert A ring slot + B regs -> fp16 buffer buf (0/1)
    #define CONVERT_CHUNK(slot, buf, breg) do {                                \
        char* srcA = smem + (slot) * A32_BYTES;                                \
        char* dstA = smem + OFF_F16 + (buf) * F16_STAGE;                       \
        char* dstB = dstA + A16_BYTES;                                         \
        _Pragma("unroll")                                                      \
        for (int i = 0; i < 4; i++) {                                          \
            const int f = tid + 256 * i;   /* float4 index, 8 per A row */     \
            float4 v = *reinterpret_cast<const float4*>(srcA + f * 16);        \
            uint2 w = make_uint2(cvt2(v.x, v.y), cvt2(v.z, v.w));              \
            *reinterpret_cast<uint2*>(dstA + (f >> 3) * A_STRIDE_B             \
                                      + (f & 7) * 8) = w;                      \
        }                                                                      \
        {                                                                      \
            uint2 w0 = make_uint2(cvt2((breg)[0].x, (breg)[0].y),              \
                                  cvt2((breg)[0].z, (breg)[0].w));             \
            uint2 w1 = make_uint2(cvt2((breg)[1].x, (breg)[1].y),              \
                                  cvt2((breg)[1].z, (breg)[1].w));             \
            *reinterpret_cast<uint2*>(dstB + b_row0 * B_STRIDE_B               \
                                      + b_col * 2) = w0;                       \
            *reinterpret_cast<uint2*>(dstB + b_row1 * B_STRIDE_B               \
                                      + b_col * 2) = w1;                       \
        }                                                                      \
    } while (0)

    // ---- prologue ----
    ISSUE_A(0, 0);
    CP_COMMIT();
    ISSUE_A(CHUNK, 1);
    CP_COMMIT();
    LDG_B(0, bcur);
    LDG_B(CHUNK, bnxt);
    CP_WAIT1();                      // own A chunk-0 copies done
    __syncthreads();                 // everyone's chunk-0 copies visible
    CONVERT_CHUNK(0, 0, bcur);
    bcur[0] = bnxt[0]; bcur[1] = bnxt[1];

    for (int c = 0; c < NCHUNK; c++) {
        // issue A chunk c+2 (slot (c+2)%3); empty commit keeps accounting uniform
        if (c + 2 < NCHUNK)
            ISSUE_A((c + 2) * CHUNK, (c + 2) % 3);
        CP_COMMIT();

        // B chunk c+2 into registers (consumed next iteration's convert)
        if (c + 2 < NCHUNK)
            LDG_B((c + 2) * CHUNK, bnxt);

        // A chunk c+1 resident (own), then barrier -> visible to all;
        // barrier also orders convert(c) [prev iter] before compute(c).
        CP_WAIT1();
        __syncthreads();

        // ---- compute chunk c from fp16 buffer (c&1) ----
        const uint32_t f16 = sbase + OFF_F16 + (uint32_t)((c & 1) * F16_STAGE);
        const uint32_t aT  = f16;
        const uint32_t bT  = f16 + A16_BYTES;

        #pragma unroll
        for (int ko = 0; ko < 2; ko++) {
            const uint32_t akb = a_lcol + (uint32_t)(ko * 32);
            uint32_t a[2][4];
            #pragma unroll
            for (int mi = 0; mi < 2; mi++) {
                const uint32_t ao = (a_lrow + mi * 16) * A_STRIDE_B + akb;
                LDSM_X4(a[mi][0], a[mi][1], a[mi][2], a[mi][3], aT + ao);
            }
            #pragma unroll
            for (int nt = 0; nt < 2; nt++) {
                const uint32_t bo = (b_lrow + (uint32_t)(ko * 16)) * B_STRIDE_B
                                    + b_lcol + (uint32_t)(nt * 32);
                uint32_t b0, b1, b2, b3;
                LDSM_X4_T(b0, b1, b2, b3, bT + bo);
                #pragma unroll
                for (int mi = 0; mi < 2; mi++) {
                    MMA16816(acc[mi][nt * 2],     a[mi][0], a[mi][1], a[mi][2], a[mi][3], b0, b1);
                    MMA16816(acc[mi][nt * 2 + 1], a[mi][0], a[mi][1], a[mi][2], a[mi][3], b2, b3);
                }
            }
        }

        // ---- convert chunk c+1 into the other fp16 buffer ----
        if (c + 1 < NCHUNK)
            CONVERT_CHUNK((c + 1) % 3, (c + 1) & 1, bcur);

        bcur[0] = bnxt[0]; bcur[1] = bnxt[1];
    }

    // ---- epilogue: scale by 1/len, store ----
    #pragma unroll
    for (int mi = 0; mi < 2; mi++) {
        const int r0 = tileM + wm * 32 + mi * 16 + (lid >> 2);
        const int r1 = r0 + 8;
        const float inv0 = 1.0f / lens[(size_t)b * E_DIM + r0];
        const float inv1 = 1.0f / lens[(size_t)b * E_DIM + r1];
        #pragma unroll
        for (int j = 0; j < 4; j++) {
            const int col = tileN + wn * 32 + j * 8 + (lid & 3) * 2;
            float2 o0 = make_float2(acc[mi][j][0] * inv0, acc[mi][j][1] * inv0);
            float2 o1 = make_float2(acc[mi][j][2] * inv1, acc[mi][j][3] * inv1);
            *reinterpret_cast<float2*>(&C[(size_t)r0 * D_DIM + col]) = o0;
            *reinterpret_cast<float2*>(&C[(size_t)r1 * D_DIM + col]) = o1;
        }
    }
}

extern "C" void kernel_launch(void* const* d_in, const int* in_sizes, int n_in,
                              void* d_out, int out_size)
{
    const float* doc  = (const float*)d_in[0];
    const float* emap = (const float*)d_in[1];
    const float* lens = (const float*)d_in[2];
    float* out = (float*)d_out;

    cudaFuncSetAttribute(mean_pool_hmma,
                         cudaFuncAttributeMaxDynamicSharedMemorySize, SMEM_TOTAL);

    dim3 grid(D_DIM / TILE_N, E_DIM / TILE_M, BATCH);   // (4, 2, 32) = 256 CTAs
    mean_pool_hmma<<<grid, 256, SMEM_TOTAL>>>(doc, emap, lens, out);
}

// round 12
// speedup vs baseline: 1.5036x; 1.0732x over previous
#include <cuda_runtime.h>
#include <cuda_fp16.h>
#include <cstdint>

// MeanPooling == batched GEMM + row scale, all-fp16 mma.sync.
// Pure register pipeline, prefetch distance 2 with staged convert:
//   iter c: compute(c) | STS packed(c+1) | cvt raw(c+2)->packed | LDG(c+3)->raw
// No cp.async, no fp32 smem staging. fp16 smem double buffer only.
//   d_in[0] doc_state      [B=32, L=2048, D=256] fp32   (B operand)
//   d_in[1] entity_mapping [B=32, E=256,  L=2048] fp32  (A operand)
//   d_in[2] entity_lens    [B=32, E=256] fp32
// Output [B, E, D] fp32 = (emap @ doc) / lens

#define BATCH 32
#define E_DIM 256
#define L_DIM 2048
#define D_DIM 256

#define TILE_M 128
#define TILE_N 64
#define CHUNK 32
#define NCHUNK (L_DIM / CHUNK)      // 64

// fp16 compute tiles (padded strides, conflict-free ldmatrix)
#define A_STRIDE_B 80                      // bytes per A row (32 halfs + pad)
#define B_STRIDE_B 144                     // bytes per B row (64 halfs + pad)
#define A16_BYTES (TILE_M * A_STRIDE_B)    // 10240
#define B16_BYTES (CHUNK * B_STRIDE_B)     // 4608
#define F16_STAGE (A16_BYTES + B16_BYTES)  // 14848
#define SMEM_TOTAL (2 * F16_STAGE)         // 29696

static __device__ __forceinline__ uint32_t smem_u32(const void* p) {
    uint32_t a;
    asm("{ .reg .u64 t; cvta.to.shared.u64 t, %1; cvt.u32.u64 %0, t; }"
        : "=r"(a) : "l"(p));
    return a;
}

#define LDSM_X4(r0, r1, r2, r3, addr) \
    asm volatile("ldmatrix.sync.aligned.m8n8.x4.shared.b16 {%0,%1,%2,%3}, [%4];" \
                 : "=r"(r0), "=r"(r1), "=r"(r2), "=r"(r3) : "r"(addr))

#define LDSM_X4_T(r0, r1, r2, r3, addr) \
    asm volatile("ldmatrix.sync.aligned.m8n8.x4.trans.shared.b16 {%0,%1,%2,%3}, [%4];" \
                 : "=r"(r0), "=r"(r1), "=r"(r2), "=r"(r3) : "r"(addr))

#define MMA16816(d, a0, a1, a2, a3, b0, b1) \
    asm volatile("mma.sync.aligned.m16n8k16.row.col.f32.f16.f16.f32 " \
                 "{%0,%1,%2,%3}, {%4,%5,%6,%7}, {%8,%9}, {%0,%1,%2,%3};" \
                 : "+f"((d)[0]), "+f"((d)[1]), "+f"((d)[2]), "+f"((d)[3]) \
                 : "r"(a0), "r"(a1), "r"(a2), "r"(a3), "r"(b0), "r"(b1))

static __device__ __forceinline__ uint32_t cvt2(float x, float y)
{
    uint32_t r;
    asm("cvt.rn.f16x2.f32 %0, %1, %2;" : "=r"(r) : "f"(y), "f"(x));
    return r;
}

__global__ void __launch_bounds__(256, 2)
mean_pool_hmma(const float* __restrict__ doc,
               const float* __restrict__ emap,
               const float* __restrict__ lens,
               float* __restrict__ out)
{
    extern __shared__ char smem[];
    const uint32_t sbase = smem_u32(smem);

    const int tid = threadIdx.x;
    const int wid = tid >> 5;
    const int lid = tid & 31;
    const int wm  = wid & 3;        // 4 warps in M (32 rows each)
    const int wn  = wid >> 2;       // 2 warps in N (32 cols each)

    const int b     = blockIdx.z;
    const int tileM = blockIdx.y * TILE_M;
    const int tileN = blockIdx.x * TILE_N;

    const float* A  = emap + (size_t)b * E_DIM * L_DIM + (size_t)tileM * L_DIM;
    const float* Bm = doc  + (size_t)b * L_DIM * D_DIM + tileN;
    float*       C  = out  + (size_t)b * E_DIM * D_DIM;

    float acc[2][4][4] = {};            // [m16-tile][n8-tile][frag]

    // gmem mapping
    const int a_r = tid >> 3;           // 0..31, +32i -> M rows
    const int a_c = (tid & 7) * 4;      // float col within chunk
    const int b_row0 = tid >> 4;        // 0..15 (K)
    const int b_row1 = (tid + 256) >> 4;// 16..31
    const int b_col  = (tid & 15) * 4;  // float col (N)

    float4  araw[4];                    // in-flight fp32 A (chunk c+2/c+3)
    uint32_t apk[8];                    // packed fp16 A (chunk c+1)
    float4  braw[2];
    uint32_t bpk[4];

    // ldmatrix lane addressing (fp16 buffers)
    const uint32_t a_lrow = (uint32_t)(wm * 32 + (lid & 15));
    const uint32_t a_lcol = (uint32_t)((lid >> 4) * 16);             // bytes
    const uint32_t b_lrow = (uint32_t)(lid & 15);
    const uint32_t b_lcol = (uint32_t)(wn * 64 + (lid >> 4) * 16);   // bytes

    #define LDG_CHUNK(k0) do {                                                 \
        _Pragma("unroll")                                                      \
        for (int i = 0; i < 4; i++)                                            \
            araw[i] = *reinterpret_cast<const float4*>(                        \
                &A[(size_t)(a_r + 32 * i) * L_DIM + (k0) + a_c]);              \
        braw[0] = *reinterpret_cast<const float4*>(                            \
            &Bm[(size_t)((k0) + b_row0) * D_DIM + b_col]);                     \
        braw[1] = *reinterpret_cast<const float4*>(                            \
            &Bm[(size_t)((k0) + b_row1) * D_DIM + b_col]);                     \
    } while (0)

    #define CVT_CHUNK() do {                                                   \
        _Pragma("unroll")                                                      \
        for (int i = 0; i < 4; i++) {                                          \
            apk[2 * i]     = cvt2(araw[i].x, araw[i].y);                       \
            apk[2 * i + 1] = cvt2(araw[i].z, araw[i].w);                       \
        }                                                                      \
        bpk[0] = cvt2(braw[0].x, braw[0].y);                                   \
        bpk[1] = cvt2(braw[0].z, braw[0].w);                                   \
        bpk[2] = cvt2(braw[1].x, braw[1].y);                                   \
        bpk[3] = cvt2(braw[1].z, braw[1].w);                                   \
    } while (0)

    #define STS_CHUNK(buf) do {                                                \
        char* dstA = smem + (buf) * F16_STAGE;                                 \
        char* dstB = dstA + A16_BYTES;                                         \
        _Pragma("unroll")                                                      \
        for (int i = 0; i < 4; i++)                                            \
            *reinterpret_cast<uint2*>(dstA + (a_r + 32 * i) * A_STRIDE_B       \
                                      + a_c * 2)                               \
                = make_uint2(apk[2 * i], apk[2 * i + 1]);                      \
        *reinterpret_cast<uint2*>(dstB + b_row0 * B_STRIDE_B + b_col * 2)      \
            = make_uint2(bpk[0], bpk[1]);                                      \
        *reinterpret_cast<uint2*>(dstB + b_row1 * B_STRIDE_B + b_col * 2)      \
            = make_uint2(bpk[2], bpk[3]);                                      \
    } while (0)

    // ---- prologue ----
    LDG_CHUNK(0);
    CVT_CHUNK();                 // chunk 0 packed (stalls on DRAM; once)
    LDG_CHUNK(CHUNK);            // chunk 1 in flight
    STS_CHUNK(0);                // chunk 0 -> buf 0
    CVT_CHUNK();                 // chunk 1 packed (stalls; prologue only)
    LDG_CHUNK(2 * CHUNK);        // chunk 2 in flight
    __syncthreads();

    for (int c = 0; c < NCHUNK; c++) {
        // ---- compute chunk c from fp16 buffer (c&1) ----
        const uint32_t f16 = sbase + (uint32_t)((c & 1) * F16_STAGE);
        const uint32_t aT  = f16;
        const uint32_t bT  = f16 + A16_BYTES;

        #pragma unroll
        for (int ko = 0; ko < 2; ko++) {
            const uint32_t akb = a_lcol + (uint32_t)(ko * 32);
            uint32_t a[2][4];
            #pragma unroll
            for (int mi = 0; mi < 2; mi++) {
                const uint32_t ao = (a_lrow + mi * 16) * A_STRIDE_B + akb;
                LDSM_X4(a[mi][0], a[mi][1], a[mi][2], a[mi][3], aT + ao);
            }
            #pragma unroll
            for (int nt = 0; nt < 2; nt++) {
                const uint32_t bo = (b_lrow + (uint32_t)(ko * 16)) * B_STRIDE_B
                                    + b_lcol + (uint32_t)(nt * 32);
                uint32_t b0, b1, b2, b3;
                LDSM_X4_T(b0, b1, b2, b3, bT + bo);
                #pragma unroll
                for (int mi = 0; mi < 2; mi++) {
                    MMA16816(acc[mi][nt * 2],     a[mi][0], a[mi][1], a[mi][2], a[mi][3], b0, b1);
                    MMA16816(acc[mi][nt * 2 + 1], a[mi][0], a[mi][1], a[mi][2], a[mi][3], b2, b3);
                }
            }
        }

        // ---- STS packed chunk c+1 into buffer (c+1)&1 ----
        if (c + 1 < NCHUNK)
            STS_CHUNK((c + 1) & 1);

        // ---- convert raw chunk c+2 (its LDG had a full iteration to land) ----
        if (c + 2 < NCHUNK)
            CVT_CHUNK();

        // ---- issue LDG for chunk c+3 ----
        if (c + 3 < NCHUNK)
            LDG_CHUNK((c + 3) * CHUNK);

        // orders: STS(c+1) before compute(c+1); compute(c) before STS(c+2)
        __syncthreads();
    }

    // ---- epilogue: scale by 1/len, store ----
    #pragma unroll
    for (int mi = 0; mi < 2; mi++) {
        const int r0 = tileM + wm * 32 + mi * 16 + (lid >> 2);
        const int r1 = r0 + 8;
        const float inv0 = 1.0f / lens[(size_t)b * E_DIM + r0];
        const float inv1 = 1.0f / lens[(size_t)b * E_DIM + r1];
        #pragma unroll
        for (int j = 0; j < 4; j++) {
            const int col = tileN + wn * 32 + j * 8 + (lid & 3) * 2;
            float2 o0 = make_float2(acc[mi][j][0] * inv0, acc[mi][j][1] * inv0);
            float2 o1 = make_float2(acc[mi][j][2] * inv1, acc[mi][j][3] * inv1);
            *reinterpret_cast<float2*>(&C[(size_t)r0 * D_DIM + col]) = o0;
            *reinterpret_cast<float2*>(&C[(size_t)r1 * D_DIM + col]) = o1;
        }
    }
}

extern "C" void kernel_launch(void* const* d_in, const int* in_sizes, int n_in,
                              void* d_out, int out_size)
{
    const float* doc  = (const float*)d_in[0];
    const float* emap = (const float*)d_in[1];
    const float* lens = (const float*)d_in[2];
    float* out = (float*)d_out;

    cudaFuncSetAttribute(mean_pool_hmma,
                         cudaFuncAttributeMaxDynamicSharedMemorySize, SMEM_TOTAL);

    dim3 grid(D_DIM / TILE_N, E_DIM / TILE_M, BATCH);   // (4, 2, 32) = 256 CTAs
    mean_pool_hmma<<<grid, 256, SMEM_TOTAL>>>(doc, emap, lens, out);
}

// round 13
// speedup vs baseline: 1.6004x; 1.0643x over previous
#include <cuda_runtime.h>
#include <cuda_fp16.h>
#include <cstdint>

// MeanPooling == batched GEMM + row scale, all-fp16 mma.sync.
// K-chunk 64, register pipeline at distance 2 with fused cvt+STS:
//   iter c: compute(c) | cvt+STS(c+1) from regs | LDG(c+2) -> regs
//   d_in[0] doc_state      [B=32, L=2048, D=256] fp32   (B operand)
//   d_in[1] entity_mapping [B=32, E=256,  L=2048] fp32  (A operand)
//   d_in[2] entity_lens    [B=32, E=256] fp32
// Output [B, E, D] fp32 = (emap @ doc) / lens

#define BATCH 32
#define E_DIM 256
#define L_DIM 2048
#define D_DIM 256

#define TILE_M 128
#define TILE_N 64
#define CHUNK 64
#define NCHUNK (L_DIM / CHUNK)      // 32

// fp16 compute tiles (row stride 144B: rows shift 16B mod 128 -> no
// ldmatrix bank conflicts; 64 halfs data + 8 pad)
#define A_STRIDE_B 144
#define B_STRIDE_B 144
#define A16_BYTES (TILE_M * A_STRIDE_B)    // 18432
#define B16_BYTES (CHUNK * B_STRIDE_B)     // 9216
#define F16_STAGE (A16_BYTES + B16_BYTES)  // 27648
#define SMEM_TOTAL (2 * F16_STAGE)         // 55296

static __device__ __forceinline__ uint32_t smem_u32(const void* p) {
    uint32_t a;
    asm("{ .reg .u64 t; cvta.to.shared.u64 t, %1; cvt.u32.u64 %0, t; }"
        : "=r"(a) : "l"(p));
    return a;
}

#define LDSM_X4(r0, r1, r2, r3, addr) \
    asm volatile("ldmatrix.sync.aligned.m8n8.x4.shared.b16 {%0,%1,%2,%3}, [%4];" \
                 : "=r"(r0), "=r"(r1), "=r"(r2), "=r"(r3) : "r"(addr))

#define LDSM_X4_T(r0, r1, r2, r3, addr) \
    asm volatile("ldmatrix.sync.aligned.m8n8.x4.trans.shared.b16 {%0,%1,%2,%3}, [%4];" \
                 : "=r"(r0), "=r"(r1), "=r"(r2), "=r"(r3) : "r"(addr))

#define MMA16816(d, a0, a1, a2, a3, b0, b1) \
    asm volatile("mma.sync.aligned.m16n8k16.row.col.f32.f16.f16.f32 " \
                 "{%0,%1,%2,%3}, {%4,%5,%6,%7}, {%8,%9}, {%0,%1,%2,%3};" \
                 : "+f"((d)[0]), "+f"((d)[1]), "+f"((d)[2]), "+f"((d)[3]) \
                 : "r"(a0), "r"(a1), "r"(a2), "r"(a3), "r"(b0), "r"(b1))

static __device__ __forceinline__ uint32_t cvt2(float x, float y)
{
    uint32_t r;
    asm("cvt.rn.f16x2.f32 %0, %1, %2;" : "=r"(r) : "f"(y), "f"(x));
    return r;
}

__global__ void __launch_bounds__(256, 2)
mean_pool_hmma(const float* __restrict__ doc,
               const float* __restrict__ emap,
               const float* __restrict__ lens,
               float* __restrict__ out)
{
    extern __shared__ char smem[];
    const uint32_t sbase = smem_u32(smem);

    const int tid = threadIdx.x;
    const int wid = tid >> 5;
    const int lid = tid & 31;
    const int wm  = wid & 3;        // 4 warps in M (32 rows each)
    const int wn  = wid >> 2;       // 2 warps in N (32 cols each)

    const int b     = blockIdx.z;
    const int tileM = blockIdx.y * TILE_M;
    const int tileN = blockIdx.x * TILE_N;

    const float* A  = emap + (size_t)b * E_DIM * L_DIM + (size_t)tileM * L_DIM;
    const float* Bm = doc  + (size_t)b * L_DIM * D_DIM + tileN;
    float*       C  = out  + (size_t)b * E_DIM * D_DIM;

    float acc[2][4][4] = {};            // [m16-tile][n8-tile][frag]

    // gmem mapping, line-coalesced (8 lanes cover one 128B line):
    // A: rows a_r+32i (i<4), float cols a_c, a_c+32  -> 8 float4/thread
    // B: rows b_r+16i (i<4), float col  b_c          -> 4 float4/thread
    const int a_r = tid >> 3;
    const int a_c = (tid & 7) * 4;
    const int b_r = tid >> 4;
    const int b_c = (tid & 15) * 4;

    float4 araw[8];
    float4 braw[4];

    // ldmatrix lane addressing (fp16 buffers)
    const uint32_t a_lrow = (uint32_t)(wm * 32 + (lid & 15));
    const uint32_t a_lcol = (uint32_t)((lid >> 4) * 16);             // bytes
    const uint32_t b_lrow = (uint32_t)(lid & 15);
    const uint32_t b_lcol = (uint32_t)(wn * 64 + (lid >> 4) * 16);   // bytes

    #define LDG_CHUNK(k0) do {                                                 \
        _Pragma("unroll")                                                      \
        for (int i = 0; i < 4; i++) {                                          \
            araw[2 * i]     = *reinterpret_cast<const float4*>(                \
                &A[(size_t)(a_r + 32 * i) * L_DIM + (k0) + a_c]);              \
            araw[2 * i + 1] = *reinterpret_cast<const float4*>(                \
                &A[(size_t)(a_r + 32 * i) * L_DIM + (k0) + a_c + 32]);         \
        }                                                                      \
        _Pragma("unroll")                                                      \
        for (int i = 0; i < 4; i++)                                            \
            braw[i] = *reinterpret_cast<const float4*>(                        \
                &Bm[(size_t)((k0) + b_r + 16 * i) * D_DIM + b_c]);             \
    } while (0)

    // fused convert + store into fp16 buffer buf (0/1)
    #define CVTSTS_CHUNK(buf) do {                                             \
        char* dstA = smem + (buf) * F16_STAGE;                                 \
        char* dstB = dstA + A16_BYTES;                                         \
        _Pragma("unroll")                                                      \
        for (int i = 0; i < 4; i++) {                                          \
            float4 v0 = araw[2 * i], v1 = araw[2 * i + 1];                     \
            *reinterpret_cast<uint2*>(dstA + (a_r + 32 * i) * A_STRIDE_B       \
                                      + a_c * 2)                               \
                = make_uint2(cvt2(v0.x, v0.y), cvt2(v0.z, v0.w));              \
            *reinterpret_cast<uint2*>(dstA + (a_r + 32 * i) * A_STRIDE_B       \
                                      + a_c * 2 + 64)                          \
                = make_uint2(cvt2(v1.x, v1.y), cvt2(v1.z, v1.w));              \
        }                                                                      \
        _Pragma("unroll")                                                      \
        for (int i = 0; i < 4; i++) {                                          \
            float4 v = braw[i];                                                \
            *reinterpret_cast<uint2*>(dstB + (b_r + 16 * i) * B_STRIDE_B       \
                                      + b_c * 2)                               \
                = make_uint2(cvt2(v.x, v.y), cvt2(v.z, v.w));                  \
        }                                                                      \
    } while (0)

    // ---- prologue ----
    LDG_CHUNK(0);
    CVTSTS_CHUNK(0);             // stalls on DRAM once
    LDG_CHUNK(CHUNK);            // chunk 1 in flight (full iter of slack)
    __syncthreads();

    for (int c = 0; c < NCHUNK; c++) {
        // ---- compute chunk c from fp16 buffer (c&1) ----
        const uint32_t f16 = sbase + (uint32_t)((c & 1) * F16_STAGE);
        const uint32_t aT  = f16;
        const uint32_t bT  = f16 + A16_BYTES;

        #pragma unroll
        for (int ko = 0; ko < 4; ko++) {            // four k16 steps
            const uint32_t akb = a_lcol + (uint32_t)(ko * 32);
            uint32_t a[2][4];
            #pragma unroll
            for (int mi = 0; mi < 2; mi++) {
                const uint32_t ao = (a_lrow + mi * 16) * A_STRIDE_B + akb;
                LDSM_X4(a[mi][0], a[mi][1], a[mi][2], a[mi][3], aT + ao);
            }
            #pragma unroll
            for (int nt = 0; nt < 2; nt++) {
                const uint32_t bo = (b_lrow + (uint32_t)(ko * 16)) * B_STRIDE_B
                                    + b_lcol + (uint32_t)(nt * 32);
                uint32_t b0, b1, b2, b3;
                LDSM_X4_T(b0, b1, b2, b3, bT + bo);
                #pragma unroll
                for (int mi = 0; mi < 2; mi++) {
                    MMA16816(acc[mi][nt * 2],     a[mi][0], a[mi][1], a[mi][2], a[mi][3], b0, b1);
                    MMA16816(acc[mi][nt * 2 + 1], a[mi][0], a[mi][1], a[mi][2], a[mi][3], b2, b3);
                }
            }
        }

        // ---- cvt+STS chunk c+1 (its LDG had a full iteration to land) ----
        if (c + 1 < NCHUNK)
            CVTSTS_CHUNK((c + 1) & 1);

        // ---- issue LDG for chunk c+2 (after STS consumed araw/braw) ----
        if (c + 2 < NCHUNK)
            LDG_CHUNK((c + 2) * CHUNK);

        // orders STS(c+1) before compute(c+1); compute(c) before STS(c+2)
        __syncthreads();
    }

    // ---- epilogue: scale by 1/len, store ----
    #pragma unroll
    for (int mi = 0; mi < 2; mi++) {
        const int r0 = tileM + wm * 32 + mi * 16 + (lid >> 2);
        const int r1 = r0 + 8;
        const float inv0 = 1.0f / lens[(size_t)b * E_DIM + r0];
        const float inv1 = 1.0f / lens[(size_t)b * E_DIM + r1];
        #pragma unroll
        for (int j = 0; j < 4; j++) {
            const int col = tileN + wn * 32 + j * 8 + (lid & 3) * 2;
            float2 o0 = make_float2(acc[mi][j][0] * inv0, acc[mi][j][1] * inv0);
            float2 o1 = make_float2(acc[mi][j][2] * inv1, acc[mi][j][3] * inv1);
            *reinterpret_cast<float2*>(&C[(size_t)r0 * D_DIM + col]) = o0;
            *reinterpret_cast<float2*>(&C[(size_t)r1 * D_DIM + col]) = o1;
        }
    }
}

extern "C" void kernel_launch(void* const* d_in, const int* in_sizes, int n_in,
                              void* d_out, int out_size)
{
    const float* doc  = (const float*)d_in[0];
    const float* emap = (const float*)d_in[1];
    const float* lens = (const float*)d_in[2];
    float* out = (float*)d_out;

    cudaFuncSetAttribute(mean_pool_hmma,
                         cudaFuncAttributeMaxDynamicSharedMemorySize, SMEM_TOTAL);

    dim3 grid(D_DIM / TILE_N, E_DIM / TILE_M, BATCH);   // (4, 2, 32) = 256 CTAs
    mean_pool_hmma<<<grid, 256, SMEM_TOTAL>>>(doc, emap, lens, out);
}

// round 14
// speedup vs baseline: 1.9038x; 1.1896x over previous
#include <cuda_runtime.h>
#include <cuda_fp16.h>
#include <cstdint>

// MeanPooling == batched GEMM + row scale, all-fp16 mma.sync.
// CTA tile 128(M) x 128(N), 512 threads (16 warps, 4M x 4N).
// K-chunk 64, register pipeline distance 2 with fused cvt+STS:
//   iter c: compute(c) | cvt+STS(c+1) from regs | LDG(c+2) -> regs
//   d_in[0] doc_state      [B=32, L=2048, D=256] fp32   (B operand)
//   d_in[1] entity_mapping [B=32, E=256,  L=2048] fp32  (A operand)
//   d_in[2] entity_lens    [B=32, E=256] fp32
// Output [B, E, D] fp32 = (emap @ doc) / lens

#define BATCH 32
#define E_DIM 256
#define L_DIM 2048
#define D_DIM 256

#define TILE_M 128
#define TILE_N 128
#define CHUNK 64
#define NCHUNK (L_DIM / CHUNK)      // 32
#define NTHREADS 512

// fp16 tiles: strides == 16 mod 128 -> conflict-free ldmatrix row phases.
#define A_STRIDE_B 144                     // 64 halfs + 8 pad
#define B_STRIDE_B 272                     // 128 halfs + 8 pad
#define A16_BYTES (TILE_M * A_STRIDE_B)    // 18432
#define B16_BYTES (CHUNK * B_STRIDE_B)     // 17408
#define F16_STAGE (A16_BYTES + B16_BYTES)  // 35840
#define SMEM_TOTAL (2 * F16_STAGE)         // 71680

static __device__ __forceinline__ uint32_t smem_u32(const void* p) {
    uint32_t a;
    asm("{ .reg .u64 t; cvta.to.shared.u64 t, %1; cvt.u32.u64 %0, t; }"
        : "=r"(a) : "l"(p));
    return a;
}

#define LDSM_X4(r0, r1, r2, r3, addr) \
    asm volatile("ldmatrix.sync.aligned.m8n8.x4.shared.b16 {%0,%1,%2,%3}, [%4];" \
                 : "=r"(r0), "=r"(r1), "=r"(r2), "=r"(r3) : "r"(addr))

#define LDSM_X4_T(r0, r1, r2, r3, addr) \
    asm volatile("ldmatrix.sync.aligned.m8n8.x4.trans.shared.b16 {%0,%1,%2,%3}, [%4];" \
                 : "=r"(r0), "=r"(r1), "=r"(r2), "=r"(r3) : "r"(addr))

#define MMA16816(d, a0, a1, a2, a3, b0, b1) \
    asm volatile("mma.sync.aligned.m16n8k16.row.col.f32.f16.f16.f32 " \
                 "{%0,%1,%2,%3}, {%4,%5,%6,%7}, {%8,%9}, {%0,%1,%2,%3};" \
                 : "+f"((d)[0]), "+f"((d)[1]), "+f"((d)[2]), "+f"((d)[3]) \
                 : "r"(a0), "r"(a1), "r"(a2), "r"(a3), "r"(b0), "r"(b1))

static __device__ __forceinline__ uint32_t cvt2(float x, float y)
{
    uint32_t r;
    asm("cvt.rn.f16x2.f32 %0, %1, %2;" : "=r"(r) : "f"(y), "f"(x));
    return r;
}

__global__ void __launch_bounds__(NTHREADS, 1)
mean_pool_hmma(const float* __restrict__ doc,
               const float* __restrict__ emap,
               const float* __restrict__ lens,
               float* __restrict__ out)
{
    extern __shared__ char smem[];
    const uint32_t sbase = smem_u32(smem);

    const int tid = threadIdx.x;
    const int wid = tid >> 5;
    const int lid = tid & 31;
    const int wm  = wid & 3;        // 4 warps in M (32 rows each)
    const int wn  = wid >> 2;       // 4 warps in N (32 cols each)

    const int b     = blockIdx.z;
    const int tileM = blockIdx.y * TILE_M;
    const int tileN = blockIdx.x * TILE_N;

    const float* A  = emap + (size_t)b * E_DIM * L_DIM + (size_t)tileM * L_DIM;
    const float* Bm = doc  + (size_t)b * L_DIM * D_DIM + tileN;
    float*       C  = out  + (size_t)b * E_DIM * D_DIM;

    float acc[2][4][4] = {};            // [m16-tile][n8-tile][frag]

    // gmem mapping (float4 units, fully coalesced):
    // A: 2048 f4/chunk, 4/thread: u = tid + 512i -> row u>>4, col16 u&15
    // B: 2048 f4/chunk, 4/thread: u = tid + 512i -> row u>>5, col16 u&31
    float4 araw[4];
    float4 braw[4];

    // ldmatrix lane addressing
    const uint32_t a_lrow = (uint32_t)(wm * 32 + (lid & 15));
    const uint32_t a_lcol = (uint32_t)((lid >> 4) * 16);              // bytes
    const uint32_t b_lrow = (uint32_t)(lid & 15);
    const uint32_t b_lcol = (uint32_t)(wn * 64 + (lid >> 4) * 16);    // bytes

    #define LDG_CHUNK(k0) do {                                                 \
        _Pragma("unroll")                                                      \
        for (int i = 0; i < 4; i++) {                                          \
            const int u = tid + 512 * i;                                       \
            araw[i] = *reinterpret_cast<const float4*>(                        \
                &A[(size_t)(u >> 4) * L_DIM + (k0) + (u & 15) * 4]);           \
        }                                                                      \
        _Pragma("unroll")                                                      \
        for (int i = 0; i < 4; i++) {                                          \
            const int u = tid + 512 * i;                                       \
            braw[i] = *reinterpret_cast<const float4*>(                        \
                &Bm[(size_t)((k0) + (u >> 5)) * D_DIM + (u & 31) * 4]);        \
        }                                                                      \
    } while (0)

    // fused convert + store into fp16 buffer buf (0/1)
    #define CVTSTS_CHUNK(buf) do {                                             \
        char* dstA = smem + (buf) * F16_STAGE;                                 \
        char* dstB = dstA + A16_BYTES;                                         \
        _Pragma("unroll")                                                      \
        for (int i = 0; i < 4; i++) {                                          \
            const int u = tid + 512 * i;                                       \
            float4 v = araw[i];                                                \
            *reinterpret_cast<uint2*>(dstA + (u >> 4) * A_STRIDE_B             \
                                      + (u & 15) * 8)                          \
                = make_uint2(cvt2(v.x, v.y), cvt2(v.z, v.w));                  \
        }                                                                      \
        _Pragma("unroll")                                                      \
        for (int i = 0; i < 4; i++) {                                          \
            const int u = tid + 512 * i;                                       \
            float4 v = braw[i];                                                \
            *reinterpret_cast<uint2*>(dstB + (u >> 5) * B_STRIDE_B             \
                                      + (u & 31) * 8)                          \
                = make_uint2(cvt2(v.x, v.y), cvt2(v.z, v.w));                  \
        }                                                                      \
    } while (0)

    // ---- prologue ----
    LDG_CHUNK(0);
    CVTSTS_CHUNK(0);             // stalls on DRAM once
    LDG_CHUNK(CHUNK);            // chunk 1 in flight (full iter of slack)
    __syncthreads();

    for (int c = 0; c < NCHUNK; c++) {
        // ---- compute chunk c from fp16 buffer (c&1) ----
        const uint32_t f16 = sbase + (uint32_t)((c & 1) * F16_STAGE);
        const uint32_t aT  = f16;
        const uint32_t bT  = f16 + A16_BYTES;

        #pragma unroll
        for (int ko = 0; ko < 4; ko++) {            // four k16 steps
            const uint32_t akb = a_lcol + (uint32_t)(ko * 32);
            uint32_t a[2][4];
            #pragma unroll
            for (int mi = 0; mi < 2; mi++) {
                const uint32_t ao = (a_lrow + mi * 16) * A_STRIDE_B + akb;
                LDSM_X4(a[mi][0], a[mi][1], a[mi][2], a[mi][3], aT + ao);
            }
            #pragma unroll
            for (int nt = 0; nt < 2; nt++) {
                const uint32_t bo = (b_lrow + (uint32_t)(ko * 16)) * B_STRIDE_B
                                    + b_lcol + (uint32_t)(nt * 32);
                uint32_t b0, b1, b2, b3;
                LDSM_X4_T(b0, b1, b2, b3, bT + bo);
                #pragma unroll
                for (int mi = 0; mi < 2; mi++) {
                    MMA16816(acc[mi][nt * 2],     a[mi][0], a[mi][1], a[mi][2], a[mi][3], b0, b1);
                    MMA16816(acc[mi][nt * 2 + 1], a[mi][0], a[mi][1], a[mi][2], a[mi][3], b2, b3);
                }
            }
        }

        // ---- cvt+STS chunk c+1 (its LDG had a full iteration to land) ----
        if (c + 1 < NCHUNK)
            CVTSTS_CHUNK((c + 1) & 1);

        // ---- issue LDG for chunk c+2 (after STS consumed araw/braw) ----
        if (c + 2 < NCHUNK)
            LDG_CHUNK((c + 2) * CHUNK);

        // orders STS(c+1) before compute(c+1); compute(c) before STS(c+2)
        __syncthreads();
    }

    // ---- epilogue: scale by 1/len, store ----
    #pragma unroll
    for (int mi = 0; mi < 2; mi++) {
        const int r0 = tileM + wm * 32 + mi * 16 + (lid >> 2);
        const int r1 = r0 + 8;
        const float inv0 = 1.0f / lens[(size_t)b * E_DIM + r0];
        const float inv1 = 1.0f / lens[(size_t)b * E_DIM + r1];
        #pragma unroll
        for (int j = 0; j < 4; j++) {
            const int col = tileN + wn * 32 + j * 8 + (lid & 3) * 2;
            float2 o0 = make_float2(acc[mi][j][0] * inv0, acc[mi][j][1] * inv0);
            float2 o1 = make_float2(acc[mi][j][2] * inv1, acc[mi][j][3] * inv1);
            *reinterpret_cast<float2*>(&C[(size_t)r0 * D_DIM + col]) = o0;
            *reinterpret_cast<float2*>(&C[(size_t)r1 * D_DIM + col]) = o1;
        }
    }
}

extern "C" void kernel_launch(void* const* d_in, const int* in_sizes, int n_in,
                              void* d_out, int out_size)
{
    const float* doc  = (const float*)d_in[0];
    const float* emap = (const float*)d_in[1];
    const float* lens = (const float*)d_in[2];
    float* out = (float*)d_out;

    cudaFuncSetAttribute(mean_pool_hmma,
                         cudaFuncAttributeMaxDynamicSharedMemorySize, SMEM_TOTAL);

    dim3 grid(D_DIM / TILE_N, E_DIM / TILE_M, BATCH);   // (2, 2, 32) = 128 CTAs
    mean_pool_hmma<<<grid, NTHREADS, SMEM_TOTAL>>>(doc, emap, lens, out);
}